// round 2
// baseline (speedup 1.0000x reference)
#include <cuda_runtime.h>
#include <cstdint>

// Embedding gather: out[row, :] = weight[idx[row], :]
// idx: 16384 values (2048*8) — int32 on device (JAX x64 disabled downcasts int64),
// weight: 50257 x 1024 fp32, out: 16384 x 1024 fp32.
// One CTA per output row; 256 threads each move one float4 (4 KB per row).

static constexpr int EMSIZE      = 1024;
static constexpr int VEC_PER_ROW = EMSIZE / 4;   // 256 float4 per row
static constexpr int VOCAB       = 50257;

__global__ __launch_bounds__(256) void embedding_gather_kernel(
    const int* __restrict__ idx,
    const float4* __restrict__ weight,
    float4* __restrict__ out,
    int n_rows)
{
    int row = blockIdx.x;
    if (row >= n_rows) return;
    int r = idx[row];                          // broadcast load (same addr per CTA)
    // Defensive clamp: a bad dtype shows as rel_err, not an illegal access.
    r = (r < 0) ? 0 : (r >= VOCAB ? VOCAB - 1 : r);
    const float4* __restrict__ src = weight + (size_t)r * VEC_PER_ROW;
    float4* __restrict__ dst = out + (size_t)row * VEC_PER_ROW;
    dst[threadIdx.x] = __ldg(&src[threadIdx.x]);
}

extern "C" void kernel_launch(void* const* d_in, const int* in_sizes, int n_in,
                              void* d_out, int out_size) {
    const int*    idx    = (const int*)d_in[0];     // input: (2048, 8) int32 on device
    const float4* weight = (const float4*)d_in[1];  // weight: (50257, 1024) fp32
    float4*       out    = (float4*)d_out;          // (2048, 8, 1024) fp32

    int n_rows = in_sizes[0];                       // 16384
    embedding_gather_kernel<<<n_rows, 256>>>(idx, weight, out, n_rows);
}

// round 3
// speedup vs baseline: 1.7040x; 1.7040x over previous
#include <cuda_runtime.h>
#include <cstdint>

// Embedding gather: out[row, :] = weight[idx[row], :]
// idx: 16384 int32, weight: 50257 x 1024 fp32, out: 16384 x 1024 fp32.
// 8 rows per CTA; each thread owns one float4 column across all 8 rows,
// issuing 8 independent LDG.128 (MLP=8) then 8 streaming STG.128.

static constexpr int EMSIZE       = 1024;
static constexpr int VEC_PER_ROW  = EMSIZE / 4;   // 256 float4 per row
static constexpr int VOCAB        = 50257;
static constexpr int ROWS_PER_CTA = 8;

__global__ __launch_bounds__(256) void embedding_gather_kernel(
    const int* __restrict__ idx,
    const float4* __restrict__ weight,
    float4* __restrict__ out,
    int n_rows)
{
    const int t    = threadIdx.x;                       // column (0..255)
    const int base = blockIdx.x * ROWS_PER_CTA;

    if (base + ROWS_PER_CTA <= n_rows) {
        // Fast path: 8 full rows.
        int r[ROWS_PER_CTA];
        #pragma unroll
        for (int i = 0; i < ROWS_PER_CTA; i++) {
            int v = __ldg(&idx[base + i]);
            r[i] = (v < 0) ? 0 : (v >= VOCAB ? VOCAB - 1 : v);
        }
        float4 w[ROWS_PER_CTA];
        #pragma unroll
        for (int i = 0; i < ROWS_PER_CTA; i++)
            w[i] = __ldg(&weight[(size_t)r[i] * VEC_PER_ROW + t]);
        #pragma unroll
        for (int i = 0; i < ROWS_PER_CTA; i++)
            __stcs(&out[(size_t)(base + i) * VEC_PER_ROW + t], w[i]);
    } else {
        // Tail (unused for 16384 rows, kept for safety).
        for (int i = 0; i < ROWS_PER_CTA; i++) {
            int row = base + i;
            if (row >= n_rows) break;
            int v = __ldg(&idx[row]);
            v = (v < 0) ? 0 : (v >= VOCAB ? VOCAB - 1 : v);
            float4 w = __ldg(&weight[(size_t)v * VEC_PER_ROW + t]);
            __stcs(&out[(size_t)row * VEC_PER_ROW + t], w);
        }
    }
}

extern "C" void kernel_launch(void* const* d_in, const int* in_sizes, int n_in,
                              void* d_out, int out_size) {
    const int*    idx    = (const int*)d_in[0];     // (2048, 8) int32 on device
    const float4* weight = (const float4*)d_in[1];  // (50257, 1024) fp32
    float4*       out    = (float4*)d_out;          // (2048, 8, 1024) fp32

    int n_rows  = in_sizes[0];                      // 16384
    int n_ctas  = (n_rows + ROWS_PER_CTA - 1) / ROWS_PER_CTA;  // 2048
    embedding_gather_kernel<<<n_ctas, 256>>>(idx, weight, out, n_rows);
}